// round 10
// baseline (speedup 1.0000x reference)
#include <cuda_runtime.h>
#include <math.h>
#include <stdint.h>

#define BSZ 2048
#define XS  256
#define HS  512
#define RS  64
#define MS  128
#define KS  64
#define HQ  128   // H/4

// ---------------- device scratch ----------------
__device__ float g_un[BSZ * MS];        // l2n(u_t)
__device__ float g_bp[7 * BSZ * HQ];    // split-K partials for base
__device__ float g_base[BSZ * HQ];
__device__ float g_kWk[MS * HQ];
__device__ float g_WmT[MS * KS];        // W_m^T (128 n x 64 k), tf32-rounded
__device__ float g_ri[BSZ * MS];
__device__ float g_r[BSZ * RS];
__device__ float g_Z[BSZ * 1536];
__device__ float g_Gx[BSZ * HS];
__device__ float g_Gh[BSZ * HS];
__device__ float g_Gr[BSZ * HS];
__device__ float g_ab[BSZ * 2];
__device__ float g_nh[BSZ * HS];
__device__ float g_hw[BSZ * RS];
__device__ float g_WT[2048 * 832];      // rows 0..1535 = W_full cols, 1536..2047 = W_full2 cols (tf32)

__device__ __forceinline__ float sigm(float v) { return 1.0f / (1.0f + expf(-v)); }
__device__ __forceinline__ float gumbelf(float u) {
    return -logf(1e-20f - logf(1e-20f + u));
}
__device__ __forceinline__ float tf32r(float v) {
    uint32_t u;
    asm("cvt.rna.tf32.f32 %0, %1;" : "=r"(u) : "f"(v));
    return __uint_as_float(u);
}
__device__ __forceinline__ uint32_t smem_u32(const void* p) {
    return (uint32_t)__cvta_generic_to_shared(p);
}

// tf32 tensor-core mma (sm_80+ PTX, compiles at compute_100)
__device__ __forceinline__ void mma16n8k8(float c[4], const uint32_t a[4],
                                          uint32_t b0, uint32_t b1) {
    asm volatile(
        "mma.sync.aligned.m16n8k8.row.col.f32.tf32.tf32.f32 "
        "{%0,%1,%2,%3}, {%4,%5,%6,%7}, {%8,%9}, {%0,%1,%2,%3};"
        : "+f"(c[0]), "+f"(c[1]), "+f"(c[2]), "+f"(c[3])
        : "r"(a[0]), "r"(a[1]), "r"(a[2]), "r"(a[3]), "r"(b0), "r"(b1));
}

// ---------------- W transpose (+ tf32 rounding) ----------------
__global__ __launch_bounds__(256) void k_transW(const float* __restrict__ Wf,
                                                const float* __restrict__ Wf2)
{
    __shared__ float tile[32][33];
    const int k0 = blockIdx.x * 32;     // 26
    const int n0 = blockIdx.y * 32;     // 64
    const int tx = threadIdx.x & 31, ty = threadIdx.x >> 5;   // 32 x 8
    const float* W; int ldw, nloc;
    if (n0 < 1536) { W = Wf;  ldw = 1536; nloc = n0; }
    else           { W = Wf2; ldw = 512;  nloc = n0 - 1536; }
#pragma unroll
    for (int i = 0; i < 32; i += 8)
        tile[ty + i][tx] = tf32r(W[(size_t)(k0 + ty + i) * ldw + nloc + tx]);
    __syncthreads();
#pragma unroll
    for (int i = 0; i < 32; i += 8)
        g_WT[(size_t)(n0 + ty + i) * 832 + k0 + tx] = tile[tx][ty + i];
}

// W_m^T: g_WmT[n][k] = tf32(W_fc[832+k][n])
__global__ void k_wmt(const float* __restrict__ W_fc)
{
    int n = blockIdx.x;       // 128
    int k = threadIdx.x;      // 64
    g_WmT[n * KS + k] = tf32r(W_fc[(size_t)(832 + k) * HQ + n]);
}

// ---------------- mma.sync tf32 GEMM (pre-headsel part) ----------------
// bx 0..11 : Z = [x|h] @ W_full[0:768]^T + bias  (K=768)
// bx 12..15: Gx = x @ W2x^T                       (K=256)
// bx 16..19: Gh = h @ W2h^T                       (K=512)
#define KCH 32
#define APAD 36
__global__ __launch_bounds__(256) void mma_pre(
    const float* __restrict__ x, const float* __restrict__ h,
    const float* __restrict__ bias,
    float* __restrict__ Zout)
{
    extern __shared__ float sm[];           // 2xA + 2xB buffers [128][APAD]
    float* Ab[2] = {sm, sm + 128 * APAD};
    float* Bb[2] = {sm + 2 * 128 * APAD, sm + 3 * 128 * APAD};

    const int t = threadIdx.x;
    const int wid = t >> 5, lane = t & 31;
    const int g = lane >> 2, tg = lane & 3;
    const int warp_m = wid & 3, warp_n = wid >> 2;   // 4 x 2 warp grid
    const int bx = blockIdx.x;
    const int mode = (bx < 12) ? 0 : (bx < 16 ? 1 : 2);   // 0=Z, 1=Gx, 2=Gh
    const int n0 = (mode == 0) ? bx * 128
                 : (mode == 1) ? 1536 + (bx - 12) * 128
                 :               1536 + (bx - 16) * 128;
    const int NT   = (mode == 0) ? 24 : (mode == 1 ? 8 : 16);
    const int boff = (mode == 2) ? 256 : 0;
    const int row0 = blockIdx.y * 128;

    const int m = t >> 1;
    const int kb = (t & 1) * 16;
    const int bidx = row0 + m;

    auto loadA16 = [&](int k0c, float4 v[4]) {
        const float* src;
        if (mode == 1)            src = x + (size_t)bidx * 256 + k0c + kb;
        else if (mode == 2)       src = h + (size_t)bidx * 512 + k0c + kb;
        else if (k0c < 256)       src = x + (size_t)bidx * 256 + k0c + kb;
        else                      src = h + (size_t)bidx * 512 + (k0c - 256) + kb;
#pragma unroll
        for (int q = 0; q < 4; q++) {
            float4 w = ((const float4*)src)[q];
            v[q] = make_float4(tf32r(w.x), tf32r(w.y), tf32r(w.z), tf32r(w.w));
        }
    };
    auto stsA = [&](int buf, const float4 v[4]) {
        float* dst = Ab[buf] + m * APAD + kb;
#pragma unroll
        for (int q = 0; q < 4; q++) *(float4*)(dst + q * 4) = v[q];
    };
    auto cpB = [&](int buf, int k0c) {
        uint32_t d = smem_u32(Bb[buf] + m * APAD + kb);
        const float* s = g_WT + (size_t)(n0 + m) * 832 + boff + k0c + kb;
#pragma unroll
        for (int q = 0; q < 4; q++)
            asm volatile("cp.async.cg.shared.global [%0], [%1], 16;"
                         :: "r"(d + q * 16), "l"(s + q * 4));
        asm volatile("cp.async.commit_group;");
    };

    float c[2][8][4];
#pragma unroll
    for (int i = 0; i < 2; i++)
#pragma unroll
        for (int j = 0; j < 8; j++)
#pragma unroll
            for (int q = 0; q < 4; q++) c[i][j][q] = 0.0f;

    {
        float4 va[4];
        loadA16(0, va);
        stsA(0, va);
        cpB(0, 0);
    }

    for (int it = 0; it < NT; it++) {
        const int buf = it & 1;
        asm volatile("cp.async.wait_group 0;");
        __syncthreads();

        float4 va[4];
        if (it + 1 < NT) {
            loadA16((it + 1) * KCH, va);
            cpB(buf ^ 1, (it + 1) * KCH);
        }

        const float* Ac = Ab[buf];
        const float* Bc = Bb[buf];
#pragma unroll
        for (int kk = 0; kk < 4; kk++) {
            const int kc = kk * 8;
            uint32_t af[2][4];
#pragma unroll
            for (int i = 0; i < 2; i++) {
                const int rb = warp_m * 32 + i * 16;
                af[i][0] = __float_as_uint(Ac[(rb + g) * APAD + kc + tg]);
                af[i][1] = __float_as_uint(Ac[(rb + g + 8) * APAD + kc + tg]);
                af[i][2] = __float_as_uint(Ac[(rb + g) * APAD + kc + tg + 4]);
                af[i][3] = __float_as_uint(Ac[(rb + g + 8) * APAD + kc + tg + 4]);
            }
#pragma unroll
            for (int j = 0; j < 8; j++) {
                const int nb = warp_n * 64 + j * 8 + g;
                uint32_t b0 = __float_as_uint(Bc[nb * APAD + kc + tg]);
                uint32_t b1 = __float_as_uint(Bc[nb * APAD + kc + tg + 4]);
                mma16n8k8(c[0][j], af[0], b0, b1);
                mma16n8k8(c[1][j], af[1], b0, b1);
            }
        }

        if (it + 1 < NT) {
            __syncthreads();
            stsA(buf ^ 1, va);
        }
    }

    float* Gdst = (mode == 1) ? g_Gx : g_Gh;
#pragma unroll
    for (int i = 0; i < 2; i++) {
        const int r0a = row0 + warp_m * 32 + i * 16 + g;
#pragma unroll
        for (int j = 0; j < 8; j++) {
            const int cl = warp_n * 64 + j * 8 + 2 * tg;
            if (mode == 0) {
                const int gcol = n0 + cl;
                float bz0 = bias[gcol], bz1 = bias[gcol + 1];
                *(float2*)(Zout + (size_t)r0a * 1536 + gcol) =
                    make_float2(c[i][j][0] + bz0, c[i][j][1] + bz1);
                *(float2*)(Zout + (size_t)(r0a + 8) * 1536 + gcol) =
                    make_float2(c[i][j][2] + bz0, c[i][j][3] + bz1);
            } else {
                const int gcol = (n0 - 1536) + cl;
                *(float2*)(Gdst + (size_t)r0a * 512 + gcol) =
                    make_float2(c[i][j][0], c[i][j][1]);
                *(float2*)(Gdst + (size_t)(r0a + 8) * 512 + gcol) =
                    make_float2(c[i][j][2], c[i][j][3]);
            }
        }
    }
}

// ---------------- rank-64 r-fix: Z += r@Wr ; Gr = r@W2r ----------------
// grid (16 n-tiles of 128 over stacked 2048, 128 b-tiles of 16)
__global__ __launch_bounds__(256) void k_rfix(float* __restrict__ Zout)
{
    __shared__ float rsm[16][64];
    const int n = blockIdx.x * 128 + (threadIdx.x & 127);
    const int b0 = blockIdx.y * 16;
    const int grp = threadIdx.x >> 7;    // 0..1
    {
        int row = threadIdx.x >> 4, q4 = (threadIdx.x & 15) * 4;
        *(float4*)&rsm[row][q4] = *(const float4*)(g_r + (size_t)(b0 + row) * RS + q4);
    }
    __syncthreads();

    float w[64];
    const float* wp = g_WT + (size_t)n * 832 + 768;
#pragma unroll
    for (int q4 = 0; q4 < 16; q4++) {
        float4 v = *(const float4*)(wp + q4 * 4);
        w[q4 * 4 + 0] = v.x; w[q4 * 4 + 1] = v.y;
        w[q4 * 4 + 2] = v.z; w[q4 * 4 + 3] = v.w;
    }
#pragma unroll
    for (int i = 0; i < 8; i++) {
        int bi = grp * 8 + i;
        float acc = 0.0f;
#pragma unroll
        for (int q = 0; q < 64; q++) acc += rsm[bi][q] * w[q];
        int b = b0 + bi;
        if (n < 1536) Zout[(size_t)b * 1536 + n] += acc;
        else          g_Gr[(size_t)b * 512 + (n - 1536)] = acc;
    }
}

// ---------------- split-K base GEMM (gathered A: x / c / l2n(u)) ----------------
__global__ __launch_bounds__(256, 2) void gemm_base(
    const float* __restrict__ x, const float* __restrict__ cc,
    const float* __restrict__ W_fc)
{
    __shared__ float As[2][8][128];
    __shared__ float Bs[2][8][128];
    const int tid = threadIdx.x;
    const int tx = tid & 15, ty = tid >> 4;
    const int s = blockIdx.x;                 // 0..6
    const int row0 = blockIdx.y * 128;
    const int cs = (s < 6) ? s * 128 : 896;   // W_fc row offset
    const int arow = tid >> 1, acol = (tid & 1) * 4;
    const int brow = tid >> 5, bcol = (tid & 31) * 4;

    const float* Asrc; int lda, off;
    if (s < 2)      { Asrc = x;    lda = 256; off = s * 128; }
    else if (s < 6) { Asrc = cc;   lda = 512; off = (s - 2) * 128; }
    else            { Asrc = g_un; lda = 128; off = 0; }

    const float* Aptr = Asrc + (size_t)(row0 + arow) * lda + off + acol;
    const float* Bptr = W_fc + (size_t)(cs + brow) * HQ + bcol;
    float* C = g_bp + (size_t)s * (BSZ * HQ);

    float acc[8][8];
#pragma unroll
    for (int i = 0; i < 8; i++)
#pragma unroll
        for (int j = 0; j < 8; j++) acc[i][j] = 0.0f;

    float4 ra = *(const float4*)Aptr;
    float4 rb = *(const float4*)Bptr;
    As[0][acol + 0][arow] = ra.x; As[0][acol + 1][arow] = ra.y;
    As[0][acol + 2][arow] = ra.z; As[0][acol + 3][arow] = ra.w;
    *(float4*)&Bs[0][brow][bcol] = rb;
    __syncthreads();

    const int nt = 128 / 8;   // 16
    for (int i = 0; i < nt; i++) {
        int cur = i & 1;
        if (i + 1 < nt) {
            ra = *(const float4*)(Aptr + (i + 1) * 8);
            rb = *(const float4*)(Bptr + (size_t)(i + 1) * 8 * HQ);
        }
#pragma unroll
        for (int kk = 0; kk < 8; kk++) {
            float4 a0 = *(const float4*)&As[cur][kk][ty * 8];
            float4 a1 = *(const float4*)&As[cur][kk][ty * 8 + 4];
            float4 b0 = *(const float4*)&Bs[cur][kk][tx * 8];
            float4 b1 = *(const float4*)&Bs[cur][kk][tx * 8 + 4];
            float av[8] = {a0.x, a0.y, a0.z, a0.w, a1.x, a1.y, a1.z, a1.w};
            float bv[8] = {b0.x, b0.y, b0.z, b0.w, b1.x, b1.y, b1.z, b1.w};
#pragma unroll
            for (int ii = 0; ii < 8; ii++)
#pragma unroll
                for (int jj = 0; jj < 8; jj++) acc[ii][jj] += av[ii] * bv[jj];
        }
        if (i + 1 < nt) {
            int nxt = cur ^ 1;
            As[nxt][acol + 0][arow] = ra.x; As[nxt][acol + 1][arow] = ra.y;
            As[nxt][acol + 2][arow] = ra.z; As[nxt][acol + 3][arow] = ra.w;
            *(float4*)&Bs[nxt][brow][bcol] = rb;
            __syncthreads();
        }
    }

#pragma unroll
    for (int i = 0; i < 8; i++) {
        float* crow = C + (size_t)(row0 + ty * 8 + i) * HQ + tx * 8;
        *(float4*)crow = make_float4(acc[i][0], acc[i][1], acc[i][2], acc[i][3]);
        *(float4*)(crow + 4) = make_float4(acc[i][4], acc[i][5], acc[i][6], acc[i][7]);
    }
}

__global__ void k_base_reduce(const float* __restrict__ b_fc)
{
    int i = blockIdx.x * 256 + threadIdx.x;
    float a = b_fc[i & 127];
#pragma unroll
    for (int s = 0; s < 7; s++) a += g_bp[(size_t)s * (BSZ * HQ) + i];
    g_base[i] = a;
}

// ---------------- fused head (tensor-core) + selection + alpha/beta ----------------
struct HSmem {
    float hm[128][68];     // exact hmem rows; stride 68 -> conflict-free frags
    float wb[128][68];     // WmT tf32 (cols 0..63 used)
    float part[128][4];    // head partials per warp_n
    float red[256];
    float ri[128];
    float rs[64];
};

__global__ __launch_bounds__(256, 2) void k_headsel(
    const float* __restrict__ x, const float* __restrict__ h,
    const float* __restrict__ hmem, const float* __restrict__ prev,
    const float* __restrict__ noise_sm, const float* __restrict__ noise_sig,
    const float* __restrict__ vec_a,
    const float* __restrict__ W_full1, const float* __restrict__ bias1,
    float* __restrict__ out)
{
    extern __shared__ char smem_raw[];
    HSmem& S = *(HSmem*)smem_raw;
    const int b = blockIdx.x;
    const int t = threadIdx.x;
    const int wid = t >> 5, lane = t & 31;
    const int g = lane >> 2, tg = lane & 3;
    const int warp_m = wid & 3, warp_n = wid >> 2;

    {
        const float4* src = (const float4*)(hmem + (size_t)b * (MS * RS));
        const float4* wsrc = (const float4*)g_WmT;
#pragma unroll
        for (int i = 0; i < 8; i++) {
            int idx = t + i * 256;
            int m = idx >> 4;
            int c4 = (idx & 15) * 4;
            *(float4*)&S.hm[m][c4] = src[idx];
            *(float4*)&S.wb[m][c4] = wsrc[idx];
        }
    }
    __syncthreads();

    float c[2][8][4];
#pragma unroll
    for (int i = 0; i < 2; i++)
#pragma unroll
        for (int j = 0; j < 8; j++)
#pragma unroll
            for (int q = 0; q < 4; q++) c[i][j][q] = 0.0f;

#pragma unroll
    for (int kk = 0; kk < 8; kk++) {
        const int kc = kk * 8;
        uint32_t af[2][4];
#pragma unroll
        for (int i = 0; i < 2; i++) {
            const int rb = warp_m * 32 + i * 16;
            af[i][0] = __float_as_uint(tf32r(S.hm[rb + g][kc + tg]));
            af[i][1] = __float_as_uint(tf32r(S.hm[rb + g + 8][kc + tg]));
            af[i][2] = __float_as_uint(tf32r(S.hm[rb + g][kc + tg + 4]));
            af[i][3] = __float_as_uint(tf32r(S.hm[rb + g + 8][kc + tg + 4]));
        }
#pragma unroll
        for (int j = 0; j < 8; j++) {
            const int nb = warp_n * 64 + j * 8 + g;
            uint32_t b0 = __float_as_uint(S.wb[nb][kc + tg]);
            uint32_t b1 = __float_as_uint(S.wb[nb][kc + tg + 4]);
            mma16n8k8(c[0][j], af[0], b0, b1);
            mma16n8k8(c[1][j], af[1], b0, b1);
        }
    }

    {
        float bse[8][2], va[8][2];
#pragma unroll
        for (int j = 0; j < 8; j++) {
            const int col = warp_n * 64 + j * 8 + 2 * tg;
            float2 bb = *(const float2*)(g_base + (size_t)b * HQ + col);
            float2 vv = *(const float2*)(vec_a + col);
            bse[j][0] = bb.x; bse[j][1] = bb.y;
            va[j][0] = vv.x;  va[j][1] = vv.y;
        }
#pragma unroll
        for (int i = 0; i < 2; i++) {
            const int r_lo = warp_m * 32 + i * 16 + g;
            const int r_hi = r_lo + 8;
            float p_lo = 0.0f, p_hi = 0.0f;
#pragma unroll
            for (int j = 0; j < 8; j++) {
                const int col = warp_n * 64 + j * 8 + 2 * tg;
                float2 klo = *(const float2*)(g_kWk + (size_t)r_lo * HQ + col);
                float2 khi = *(const float2*)(g_kWk + (size_t)r_hi * HQ + col);
                p_lo += tanhf(c[i][j][0] + bse[j][0] + klo.x) * va[j][0]
                      + tanhf(c[i][j][1] + bse[j][1] + klo.y) * va[j][1];
                p_hi += tanhf(c[i][j][2] + bse[j][0] + khi.x) * va[j][0]
                      + tanhf(c[i][j][3] + bse[j][1] + khi.y) * va[j][1];
            }
            p_lo += __shfl_xor_sync(0xffffffffu, p_lo, 1);
            p_lo += __shfl_xor_sync(0xffffffffu, p_lo, 2);
            p_hi += __shfl_xor_sync(0xffffffffu, p_hi, 1);
            p_hi += __shfl_xor_sync(0xffffffffu, p_hi, 2);
            if (tg == 0) {
                S.part[r_lo][warp_n] = p_lo;
                S.part[r_hi][warp_n] = p_hi;
            }
        }
    }
    __syncthreads();

    float hv = 0.0f;
    if (t < MS) {
        hv = S.part[t][0] + S.part[t][1];
        hv -= prev[(size_t)b * MS + t] * 100.0f;
    }
    {
        float v = (t < MS) ? hv * hv : 0.0f;
        S.red[t] = v; __syncthreads();
        for (int s = 128; s > 0; s >>= 1) {
            if (t < s) S.red[t] += S.red[t + s];
            __syncthreads();
        }
        float nrm = fmaxf(sqrtf(S.red[0]), 1e-12f);
        __syncthreads();
        if (t < MS) hv /= nrm;
    }
    float z = (t < MS) ? hv + gumbelf(noise_sm[(size_t)b * MS + t]) : -INFINITY;
    float y = 0.0f;
    {
        S.red[t] = z; __syncthreads();
        for (int s = 128; s > 0; s >>= 1) {
            if (t < s) S.red[t] = fmaxf(S.red[t], S.red[t + s]);
            __syncthreads();
        }
        float zmax = S.red[0]; __syncthreads();
        float e = (t < MS) ? expf(z - zmax) : 0.0f;
        S.red[t] = e; __syncthreads();
        for (int s = 128; s > 0; s >>= 1) {
            if (t < s) S.red[t] += S.red[t + s];
            __syncthreads();
        }
        float es = S.red[0]; __syncthreads();
        y = e / es;
        S.red[t] = (t < MS) ? y : 0.0f; __syncthreads();
        for (int s = 128; s > 0; s >>= 1) {
            if (t < s) S.red[t] = fmaxf(S.red[t], S.red[t + s]);
            __syncthreads();
        }
        float ymax = S.red[0]; __syncthreads();
        if (t < MS) {
            float hard = (y == ymax) ? 1.0f : 0.0f;
            float ri = (hard - y) + y;      // exactly 0 off-support
            S.ri[t] = ri;
            g_ri[(size_t)b * MS + t] = ri;
        }
    }
    __syncthreads();

    if (t < RS) {
        float a = 0.0f;
#pragma unroll 8
        for (int m = 0; m < MS; m++) a += S.ri[m] * S.hm[m][t];
        S.rs[t] = a;
        g_r[(size_t)b * RS + t] = a;
        out[(size_t)b * 576 + HS + t] = a;
    }
    __syncthreads();

    {
        float s0 = 0.0f, s1 = 0.0f;
        for (int cI = t; cI < 832; cI += 256) {
            float v;
            if (cI < 256)      v = x[(size_t)b * XS + cI];
            else if (cI < 768) v = h[(size_t)b * HS + (cI - 256)];
            else               v = S.rs[cI - 768];
            s0 += v * W_full1[cI * 2 + 0];
            s1 += v * W_full1[cI * 2 + 1];
        }
        S.red[t] = s0; __syncthreads();
        for (int s = 128; s > 0; s >>= 1) {
            if (t < s) S.red[t] += S.red[t + s];
            __syncthreads();
        }
        float S0 = S.red[0]; __syncthreads();
        S.red[t] = s1; __syncthreads();
        for (int s = 128; s > 0; s >>= 1) {
            if (t < s) S.red[t] += S.red[t + s];
            __syncthreads();
        }
        float S1 = S.red[0];
        if (t == 0)
            g_ab[b * 2 + 0] = sigm((S0 + bias1[0] + gumbelf(noise_sig[b * 2 + 0])) * (10.0f / 3.0f));
        if (t == 1)
            g_ab[b * 2 + 1] = sigm((S1 + bias1[1] + gumbelf(noise_sig[b * 2 + 1])) * (10.0f / 3.0f));
    }
}

// ---------------- small kernels ----------------
__global__ void k_prep(const float* __restrict__ u)
{
    __shared__ float red[128];
    int b = blockIdx.x, t = threadIdx.x;
    float uv = u[b * MS + t];
    red[t] = uv * uv; __syncthreads();
    for (int s = 64; s > 0; s >>= 1) {
        if (t < s) red[t] += red[t + s];
        __syncthreads();
    }
    float denom = fmaxf(sqrtf(red[0]), 1e-12f);
    g_un[b * MS + t] = uv / denom;
}

__global__ void k_kwk(const float* __restrict__ keys, const float* __restrict__ W_fc)
{
    int m = blockIdx.x, t = threadIdx.x;
    float a = 0.0f;
#pragma unroll 8
    for (int r = 0; r < KS; r++)
        a += keys[m * KS + r] * W_fc[(768 + r) * HQ + t];
    g_kWk[m * HQ + t] = a;
}

__global__ void k_epi(const float* __restrict__ c, const float* __restrict__ bias2,
                      float* __restrict__ out)
{
    int b = blockIdx.x, t = threadIdx.x;   // 256 threads
    float al = g_ab[b * 2 + 0];
    float be = g_ab[b * 2 + 1];
    for (int j = t; j < HS; j += 256) {
        size_t bj = (size_t)b * HS + j;
        float pre = g_Gx[bj] + al * g_Gh[bj] + be * g_Gr[bj] + bias2[j];
        float nc0 = tanhf(pre);
        float zi = g_Z[(size_t)b * 1536 + j];
        float zf = g_Z[(size_t)b * 1536 + 512 + j];
        float zo = g_Z[(size_t)b * 1536 + 1024 + j];
        float cc = c[bj];
        float ncv = cc * sigm(zf + 1.0f) + sigm(zi) * nc0;
        float nh = tanhf(ncv) * sigm(zo);
        out[(size_t)b * 576 + j] = nh;
        g_nh[bj] = nh;
    }
}

__global__ __launch_bounds__(256) void k_hw(
    const float* __restrict__ x, const float* __restrict__ W_fc1,
    const float* __restrict__ b_fc1)
{
    __shared__ float Ws[64][64];
    __shared__ float Asb[16][68];
    const int b0 = blockIdx.x * 16;
    const int t = threadIdx.x;
    const int n = t & 63, bl = t >> 6;
    float acc[4] = {0.0f, 0.0f, 0.0f, 0.0f};

    for (int k0 = 0; k0 < 768; k0 += 64) {
#pragma unroll
        for (int i = 0; i < 4; i++) {
            int idx = t + i * 256;
            int row = idx >> 4, c4 = (idx & 15) * 4;
            *(float4*)&Ws[row][c4] = *(const float4*)(W_fc1 + (size_t)(k0 + row) * RS + c4);
        }
        {
            int idx = t;
            int row = idx >> 4, c4 = (idx & 15) * 4;
            int gb = b0 + row, gk = k0 + c4;
            float4 v;
            if (gk < 256) v = *(const float4*)(x + (size_t)gb * XS + gk);
            else          v = *(const float4*)(g_nh + (size_t)gb * HS + (gk - 256));
            *(float4*)&Asb[row][c4] = v;
        }
        __syncthreads();
#pragma unroll 16
        for (int kk = 0; kk < 64; kk++) {
            float w = Ws[kk][n];
#pragma unroll
            for (int i = 0; i < 4; i++) acc[i] += Asb[bl * 4 + i][kk] * w;
        }
        __syncthreads();
    }
    float bb = b_fc1[n];
#pragma unroll
    for (int i = 0; i < 4; i++)
        g_hw[(size_t)(b0 + bl * 4 + i) * RS + n] = acc[i] + bb;
}

__global__ void k_hmem_copy(const float* __restrict__ hmem, float* __restrict__ out)
{
    size_t idx = (size_t)blockIdx.x * 256 + threadIdx.x;
    ((float4*)out)[(size_t)(BSZ * 576 / 4) + idx] = ((const float4*)hmem)[idx];
}

__global__ void k_hmem_fix(const float* __restrict__ hmem, float* __restrict__ out)
{
    __shared__ float w[128];
    const int b = blockIdx.x, t = threadIdx.x;
    w[t] = g_ri[(size_t)b * MS + t];
    __syncthreads();
    for (int m = 0; m < MS; m++) {
        float wm = w[m];
        if (wm != 0.0f && t < RS) {
            float hv = hmem[((size_t)b * MS + m) * RS + t];
            float hwv = g_hw[(size_t)b * RS + t];
            out[(size_t)BSZ * 576 + ((size_t)b * MS + m) * RS + t] =
                hwv * wm + hv * (1.0f - wm);
        }
    }
}

// ---------------- launch ----------------
extern "C" void kernel_launch(void* const* d_in, const int* in_sizes, int n_in,
                              void* d_out, int out_size)
{
    const float* x        = (const float*)d_in[0];
    const float* h        = (const float*)d_in[1];
    const float* c        = (const float*)d_in[2];
    const float* hmem     = (const float*)d_in[3];
    const float* u_t      = (const float*)d_in[4];
    const float* prev     = (const float*)d_in[5];
    const float* W_full   = (const float*)d_in[6];
    const float* bias     = (const float*)d_in[7];
    const float* W_full1  = (const float*)d_in[8];
    const float* bias1    = (const float*)d_in[9];
    const float* W_full2  = (const float*)d_in[10];
    const float* bias2    = (const float*)d_in[11];
    const float* keys     = (const float*)d_in[12];
    const float* vec_a    = (const float*)d_in[13];
    const float* W_fc     = (const float*)d_in[14];
    const float* b_fc     = (const float*)d_in[15];
    const float* W_fc1    = (const float*)d_in[16];
    const float* b_fc1    = (const float*)d_in[17];
    const float* noise_sm = (const float*)d_in[18];
    const float* noise_sig= (const float*)d_in[19];
    float* out = (float*)d_out;

    float* p_Z;
    cudaGetSymbolAddress((void**)&p_Z, g_Z);

    const int MMASMEM = 4 * 128 * APAD * 4;   // 73728 B

    static cudaStream_t s2 = nullptr, s3 = nullptr;
    static cudaEvent_t e1 = nullptr, e2 = nullptr, e_wk = nullptr, e_pre = nullptr;
    static bool init_done = false;
    if (!init_done) {
        cudaFuncSetAttribute(k_headsel, cudaFuncAttributeMaxDynamicSharedMemorySize,
                             (int)sizeof(HSmem));
        cudaFuncSetAttribute(mma_pre, cudaFuncAttributeMaxDynamicSharedMemorySize, MMASMEM);
        cudaStreamCreateWithFlags(&s2, cudaStreamNonBlocking);
        cudaStreamCreateWithFlags(&s3, cudaStreamNonBlocking);
        cudaEventCreateWithFlags(&e1, cudaEventDisableTiming);
        cudaEventCreateWithFlags(&e2, cudaEventDisableTiming);
        cudaEventCreateWithFlags(&e_wk, cudaEventDisableTiming);
        cudaEventCreateWithFlags(&e_pre, cudaEventDisableTiming);
        init_done = true;
    }

    // fork
    cudaEventRecord(e1, 0);
    cudaStreamWaitEvent(s2, e1, 0);
    cudaStreamWaitEvent(s3, e1, 0);

    // s2: bulk hmem copy (no deps)
    k_hmem_copy<<<(BSZ * MS * 16) / 256, 256, 0, s2>>>(hmem, out);
    cudaEventRecord(e2, s2);

    // s3: weight prep, then the big x/h MMA (independent of headsel)
    k_transW<<<dim3(26, 64), 256, 0, s3>>>(W_full, W_full2);
    k_kwk<<<MS, HQ, 0, s3>>>(keys, W_fc);
    k_wmt<<<MS, KS, 0, s3>>>(W_fc);
    cudaEventRecord(e_wk, s3);
    mma_pre<<<dim3(20, 16), 256, MMASMEM, s3>>>(x, h, bias, p_Z);
    cudaEventRecord(e_pre, s3);

    // main chain
    k_prep<<<BSZ, 128>>>(u_t);
    gemm_base<<<dim3(7, 16), 256>>>(x, c, W_fc);
    k_base_reduce<<<BSZ * HQ / 256, 256>>>(b_fc);

    cudaStreamWaitEvent(0, e_wk, 0);
    k_headsel<<<BSZ, 256, sizeof(HSmem)>>>(x, h, hmem, prev, noise_sm, noise_sig,
                                           vec_a, W_full1, bias1, out);

    cudaStreamWaitEvent(0, e_pre, 0);
    k_rfix<<<dim3(16, 128), 256>>>(p_Z);
    k_epi<<<BSZ, 256>>>(c, bias2, out);
    k_hw<<<BSZ / 16, 256>>>(x, W_fc1, b_fc1);

    cudaStreamWaitEvent(0, e2, 0);
    k_hmem_fix<<<BSZ, 128>>>(hmem, out);
}

// round 12
// speedup vs baseline: 1.1231x; 1.1231x over previous
#include <cuda_runtime.h>
#include <math.h>
#include <stdint.h>

#define BSZ 2048
#define XS  256
#define HS  512
#define RS  64
#define MS  128
#define KS  64
#define HQ  128   // H/4

// ---------------- device scratch ----------------
__device__ float g_un[BSZ * MS];        // l2n(u_t)
__device__ float g_bp[7 * BSZ * HQ];    // split-K partials for base
__device__ float g_kWk[MS * HQ];
__device__ float g_WmT[MS * KS];        // W_m^T (128 n x 64 k), tf32-rounded
__device__ float g_ri[BSZ * MS];
__device__ float g_r[BSZ * RS];
__device__ float g_Z[BSZ * 1536];
__device__ float g_G[BSZ * HS];
__device__ float g_ab[BSZ * 2];
__device__ float g_nh[BSZ * HS];
__device__ float g_hw[BSZ * RS];
__device__ float g_WT[2048 * 832];      // rows 0..1535 = W_full cols, 1536..2047 = W_full2 cols (tf32)

__device__ __forceinline__ float sigm(float v) { return 1.0f / (1.0f + expf(-v)); }
__device__ __forceinline__ float gumbelf(float u) {
    return -logf(1e-20f - logf(1e-20f + u));
}
__device__ __forceinline__ float tf32r(float v) {
    uint32_t u;
    asm("cvt.rna.tf32.f32 %0, %1;" : "=r"(u) : "f"(v));
    return __uint_as_float(u);
}
__device__ __forceinline__ uint32_t smem_u32(const void* p) {
    return (uint32_t)__cvta_generic_to_shared(p);
}

// tf32 tensor-core mma (sm_80+ PTX, compiles at compute_100)
__device__ __forceinline__ void mma16n8k8(float c[4], const uint32_t a[4],
                                          uint32_t b0, uint32_t b1) {
    asm volatile(
        "mma.sync.aligned.m16n8k8.row.col.f32.tf32.tf32.f32 "
        "{%0,%1,%2,%3}, {%4,%5,%6,%7}, {%8,%9}, {%0,%1,%2,%3};"
        : "+f"(c[0]), "+f"(c[1]), "+f"(c[2]), "+f"(c[3])
        : "r"(a[0]), "r"(a[1]), "r"(a[2]), "r"(a[3]), "r"(b0), "r"(b1));
}

// ---------------- W transpose (+ tf32 rounding) ----------------
__global__ __launch_bounds__(256) void k_transW(const float* __restrict__ Wf,
                                                const float* __restrict__ Wf2)
{
    __shared__ float tile[32][33];
    const int k0 = blockIdx.x * 32;     // 26
    const int n0 = blockIdx.y * 32;     // 64
    const int tx = threadIdx.x & 31, ty = threadIdx.x >> 5;   // 32 x 8
    const float* W; int ldw, nloc;
    if (n0 < 1536) { W = Wf;  ldw = 1536; nloc = n0; }
    else           { W = Wf2; ldw = 512;  nloc = n0 - 1536; }
#pragma unroll
    for (int i = 0; i < 32; i += 8)
        tile[ty + i][tx] = tf32r(W[(size_t)(k0 + ty + i) * ldw + nloc + tx]);
    __syncthreads();
#pragma unroll
    for (int i = 0; i < 32; i += 8)
        g_WT[(size_t)(n0 + ty + i) * 832 + k0 + tx] = tile[tx][ty + i];
}

// W_m^T: g_WmT[n][k] = tf32(W_fc[832+k][n])
__global__ void k_wmt(const float* __restrict__ W_fc)
{
    int n = blockIdx.x;       // 128
    int k = threadIdx.x;      // 64
    g_WmT[n * KS + k] = tf32r(W_fc[(size_t)(832 + k) * HQ + n]);
}

// ---------------- mma.sync tf32 GEMM: Z (N=1536) + scaled-G (N=512) ----------------
#define KCH 32
#define APAD 36
__global__ __launch_bounds__(256) void mma_big(
    const float* __restrict__ x, const float* __restrict__ h,
    const float* __restrict__ rbuf, const float* __restrict__ ab,
    const float* __restrict__ bias,
    float* __restrict__ Zout, float* __restrict__ Gout)
{
    extern __shared__ float sm[];           // [2][128][APAD] A + [2][128][APAD] B
    float* Ab[2] = {sm, sm + 128 * APAD};
    float* Bb[2] = {sm + 2 * 128 * APAD, sm + 3 * 128 * APAD};

    const int t = threadIdx.x;
    const int wid = t >> 5, lane = t & 31;
    const int g = lane >> 2, tg = lane & 3;
    const int warp_m = wid & 3, warp_n = wid >> 2;   // 4 x 2 warp grid
    const bool isG = blockIdx.x >= 12;
    const int n0 = blockIdx.x * 128;
    const int row0 = blockIdx.y * 128;

    const int m = t >> 1;
    const int kb = (t & 1) * 16;
    const int bidx = row0 + m;
    float alpha = 1.0f, beta = 1.0f;
    if (isG) { alpha = ab[bidx * 2]; beta = ab[bidx * 2 + 1]; }

    auto loadA16 = [&](int k0c, float4 v[4]) {
        const float* src; float sc;
        if (k0c < 256)      { src = x    + (size_t)bidx * 256 + k0c + kb;         sc = 1.0f;  }
        else if (k0c < 768) { src = h    + (size_t)bidx * 512 + (k0c - 256) + kb; sc = alpha; }
        else                { src = rbuf + (size_t)bidx * 64  + (k0c - 768) + kb; sc = beta;  }
#pragma unroll
        for (int q = 0; q < 4; q++) {
            float4 w = ((const float4*)src)[q];
            v[q] = make_float4(tf32r(w.x * sc), tf32r(w.y * sc),
                               tf32r(w.z * sc), tf32r(w.w * sc));
        }
    };
    auto stsA = [&](int buf, const float4 v[4]) {
        float* dst = Ab[buf] + m * APAD + kb;
#pragma unroll
        for (int q = 0; q < 4; q++) *(float4*)(dst + q * 4) = v[q];
    };
    auto cpB = [&](int buf, int k0c) {
        uint32_t d = smem_u32(Bb[buf] + m * APAD + kb);
        const float* s = g_WT + (size_t)(n0 + m) * 832 + k0c + kb;
#pragma unroll
        for (int q = 0; q < 4; q++)
            asm volatile("cp.async.cg.shared.global [%0], [%1], 16;"
                         :: "r"(d + q * 16), "l"(s + q * 4));
        asm volatile("cp.async.commit_group;");
    };

    float c[2][8][4];
#pragma unroll
    for (int i = 0; i < 2; i++)
#pragma unroll
        for (int j = 0; j < 8; j++)
#pragma unroll
            for (int q = 0; q < 4; q++) c[i][j][q] = 0.0f;

    {
        float4 va[4];
        loadA16(0, va);
        stsA(0, va);
        cpB(0, 0);
    }

    const int NT = 832 / KCH;   // 26
    for (int it = 0; it < NT; it++) {
        const int buf = it & 1;
        asm volatile("cp.async.wait_group 0;");
        __syncthreads();

        float4 va[4];
        if (it + 1 < NT) {
            loadA16((it + 1) * KCH, va);
            cpB(buf ^ 1, (it + 1) * KCH);
        }

        const float* Ac = Ab[buf];
        const float* Bc = Bb[buf];
#pragma unroll
        for (int kk = 0; kk < 4; kk++) {
            const int kc = kk * 8;
            uint32_t af[2][4];
#pragma unroll
            for (int i = 0; i < 2; i++) {
                const int rb = warp_m * 32 + i * 16;
                af[i][0] = __float_as_uint(Ac[(rb + g) * APAD + kc + tg]);
                af[i][1] = __float_as_uint(Ac[(rb + g + 8) * APAD + kc + tg]);
                af[i][2] = __float_as_uint(Ac[(rb + g) * APAD + kc + tg + 4]);
                af[i][3] = __float_as_uint(Ac[(rb + g + 8) * APAD + kc + tg + 4]);
            }
#pragma unroll
            for (int j = 0; j < 8; j++) {
                const int nb = warp_n * 64 + j * 8 + g;
                uint32_t b0 = __float_as_uint(Bc[nb * APAD + kc + tg]);
                uint32_t b1 = __float_as_uint(Bc[nb * APAD + kc + tg + 4]);
                mma16n8k8(c[0][j], af[0], b0, b1);
                mma16n8k8(c[1][j], af[1], b0, b1);
            }
        }

        if (it + 1 < NT) {
            __syncthreads();
            stsA(buf ^ 1, va);
        }
    }

#pragma unroll
    for (int i = 0; i < 2; i++) {
        const int r0a = row0 + warp_m * 32 + i * 16 + g;
#pragma unroll
        for (int j = 0; j < 8; j++) {
            const int cl = warp_n * 64 + j * 8 + 2 * tg;
            if (!isG) {
                const int gcol = n0 + cl;
                float bz0 = bias[gcol], bz1 = bias[gcol + 1];
                *(float2*)(Zout + (size_t)r0a * 1536 + gcol) =
                    make_float2(c[i][j][0] + bz0, c[i][j][1] + bz1);
                *(float2*)(Zout + (size_t)(r0a + 8) * 1536 + gcol) =
                    make_float2(c[i][j][2] + bz0, c[i][j][3] + bz1);
            } else {
                const int gcol = (n0 - 1536) + cl;
                *(float2*)(Gout + (size_t)r0a * 512 + gcol) =
                    make_float2(c[i][j][0], c[i][j][1]);
                *(float2*)(Gout + (size_t)(r0a + 8) * 512 + gcol) =
                    make_float2(c[i][j][2], c[i][j][3]);
            }
        }
    }
}

// ---------------- split-K base GEMM (gathered A: x / c / l2n(u)) ----------------
__global__ __launch_bounds__(256, 2) void gemm_base(
    const float* __restrict__ x, const float* __restrict__ cc,
    const float* __restrict__ W_fc)
{
    __shared__ float As[2][8][128];
    __shared__ float Bs[2][8][128];
    const int tid = threadIdx.x;
    const int tx = tid & 15, ty = tid >> 4;
    const int s = blockIdx.x;                 // 0..6
    const int row0 = blockIdx.y * 128;
    const int cs = (s < 6) ? s * 128 : 896;   // W_fc row offset
    const int arow = tid >> 1, acol = (tid & 1) * 4;
    const int brow = tid >> 5, bcol = (tid & 31) * 4;

    const float* Asrc; int lda, off;
    if (s < 2)      { Asrc = x;    lda = 256; off = s * 128; }
    else if (s < 6) { Asrc = cc;   lda = 512; off = (s - 2) * 128; }
    else            { Asrc = g_un; lda = 128; off = 0; }

    const float* Aptr = Asrc + (size_t)(row0 + arow) * lda + off + acol;
    const float* Bptr = W_fc + (size_t)(cs + brow) * HQ + bcol;
    float* C = g_bp + (size_t)s * (BSZ * HQ);

    float acc[8][8];
#pragma unroll
    for (int i = 0; i < 8; i++)
#pragma unroll
        for (int j = 0; j < 8; j++) acc[i][j] = 0.0f;

    float4 ra = *(const float4*)Aptr;
    float4 rb = *(const float4*)Bptr;
    As[0][acol + 0][arow] = ra.x; As[0][acol + 1][arow] = ra.y;
    As[0][acol + 2][arow] = ra.z; As[0][acol + 3][arow] = ra.w;
    *(float4*)&Bs[0][brow][bcol] = rb;
    __syncthreads();

    const int nt = 128 / 8;   // 16
    for (int i = 0; i < nt; i++) {
        int cur = i & 1;
        if (i + 1 < nt) {
            ra = *(const float4*)(Aptr + (i + 1) * 8);
            rb = *(const float4*)(Bptr + (size_t)(i + 1) * 8 * HQ);
        }
#pragma unroll
        for (int kk = 0; kk < 8; kk++) {
            float4 a0 = *(const float4*)&As[cur][kk][ty * 8];
            float4 a1 = *(const float4*)&As[cur][kk][ty * 8 + 4];
            float4 b0 = *(const float4*)&Bs[cur][kk][tx * 8];
            float4 b1 = *(const float4*)&Bs[cur][kk][tx * 8 + 4];
            float av[8] = {a0.x, a0.y, a0.z, a0.w, a1.x, a1.y, a1.z, a1.w};
            float bv[8] = {b0.x, b0.y, b0.z, b0.w, b1.x, b1.y, b1.z, b1.w};
#pragma unroll
            for (int ii = 0; ii < 8; ii++)
#pragma unroll
                for (int jj = 0; jj < 8; jj++) acc[ii][jj] += av[ii] * bv[jj];
        }
        if (i + 1 < nt) {
            int nxt = cur ^ 1;
            As[nxt][acol + 0][arow] = ra.x; As[nxt][acol + 1][arow] = ra.y;
            As[nxt][acol + 2][arow] = ra.z; As[nxt][acol + 3][arow] = ra.w;
            *(float4*)&Bs[nxt][brow][bcol] = rb;
            __syncthreads();
        }
    }

#pragma unroll
    for (int i = 0; i < 8; i++) {
        float* crow = C + (size_t)(row0 + ty * 8 + i) * HQ + tx * 8;
        *(float4*)crow = make_float4(acc[i][0], acc[i][1], acc[i][2], acc[i][3]);
        *(float4*)(crow + 4) = make_float4(acc[i][4], acc[i][5], acc[i][6], acc[i][7]);
    }
}

// ---------------- fused head (tensor-core) + selection + alpha/beta ----------------
// Base partial-sum reduction folded into the load phase (no k_base_reduce kernel).
struct HSmem {
    float hm[128][68];     // exact hmem rows; stride 68 -> conflict-free frags
    float wb[128][68];     // WmT tf32 (cols 0..63 used)
    float bse[128];        // base[b][:] reduced from 7 split-K partials + b_fc
    float part[128][4];    // head partials per warp_n
    float red[256];
    float ri[128];
    float rs[64];
};

__global__ __launch_bounds__(256, 2) void k_headsel(
    const float* __restrict__ x, const float* __restrict__ h,
    const float* __restrict__ hmem, const float* __restrict__ prev,
    const float* __restrict__ noise_sm, const float* __restrict__ noise_sig,
    const float* __restrict__ vec_a, const float* __restrict__ b_fc,
    const float* __restrict__ W_full1, const float* __restrict__ bias1,
    float* __restrict__ out)
{
    extern __shared__ char smem_raw[];
    HSmem& S = *(HSmem*)smem_raw;
    const int b = blockIdx.x;
    const int t = threadIdx.x;
    const int wid = t >> 5, lane = t & 31;
    const int g = lane >> 2, tg = lane & 3;
    const int warp_m = wid & 3, warp_n = wid >> 2;

    // load hmem[b] (exact) and WmT (tf32) into smem; reduce base partials
    {
        const float4* src = (const float4*)(hmem + (size_t)b * (MS * RS));
        const float4* wsrc = (const float4*)g_WmT;
#pragma unroll
        for (int i = 0; i < 8; i++) {
            int idx = t + i * 256;
            int m = idx >> 4;
            int c4 = (idx & 15) * 4;
            *(float4*)&S.hm[m][c4] = src[idx];
            *(float4*)&S.wb[m][c4] = wsrc[idx];
        }
        if (t < HQ) {
            float a = b_fc[t];
#pragma unroll
            for (int s = 0; s < 7; s++)
                a += g_bp[(size_t)s * (BSZ * HQ) + (size_t)b * HQ + t];
            S.bse[t] = a;
        }
    }
    __syncthreads();

    float c[2][8][4];
#pragma unroll
    for (int i = 0; i < 2; i++)
#pragma unroll
        for (int j = 0; j < 8; j++)
#pragma unroll
            for (int q = 0; q < 4; q++) c[i][j][q] = 0.0f;

#pragma unroll
    for (int kk = 0; kk < 8; kk++) {
        const int kc = kk * 8;
        uint32_t af[2][4];
#pragma unroll
        for (int i = 0; i < 2; i++) {
            const int rb = warp_m * 32 + i * 16;
            af[i][0] = __float_as_uint(tf32r(S.hm[rb + g][kc + tg]));
            af[i][1] = __float_as_uint(tf32r(S.hm[rb + g + 8][kc + tg]));
            af[i][2] = __float_as_uint(tf32r(S.hm[rb + g][kc + tg + 4]));
            af[i][3] = __float_as_uint(tf32r(S.hm[rb + g + 8][kc + tg + 4]));
        }
#pragma unroll
        for (int j = 0; j < 8; j++) {
            const int nb = warp_n * 64 + j * 8 + g;
            uint32_t b0 = __float_as_uint(S.wb[nb][kc + tg]);
            uint32_t b1 = __float_as_uint(S.wb[nb][kc + tg + 4]);
            mma16n8k8(c[0][j], af[0], b0, b1);
            mma16n8k8(c[1][j], af[1], b0, b1);
        }
    }

    // epilogue: tanh(hid + base + kWk) * vec_a, reduce over kq
    {
        float bse[8][2], va[8][2];
#pragma unroll
        for (int j = 0; j < 8; j++) {
            const int col = warp_n * 64 + j * 8 + 2 * tg;
            bse[j][0] = S.bse[col];
            bse[j][1] = S.bse[col + 1];
            float2 vv = *(const float2*)(vec_a + col);
            va[j][0] = vv.x;  va[j][1] = vv.y;
        }
#pragma unroll
        for (int i = 0; i < 2; i++) {
            const int r_lo = warp_m * 32 + i * 16 + g;
            const int r_hi = r_lo + 8;
            float p_lo = 0.0f, p_hi = 0.0f;
#pragma unroll
            for (int j = 0; j < 8; j++) {
                const int col = warp_n * 64 + j * 8 + 2 * tg;
                float2 klo = *(const float2*)(g_kWk + (size_t)r_lo * HQ + col);
                float2 khi = *(const float2*)(g_kWk + (size_t)r_hi * HQ + col);
                p_lo += tanhf(c[i][j][0] + bse[j][0] + klo.x) * va[j][0]
                      + tanhf(c[i][j][1] + bse[j][1] + klo.y) * va[j][1];
                p_hi += tanhf(c[i][j][2] + bse[j][0] + khi.x) * va[j][0]
                      + tanhf(c[i][j][3] + bse[j][1] + khi.y) * va[j][1];
            }
            p_lo += __shfl_xor_sync(0xffffffffu, p_lo, 1);
            p_lo += __shfl_xor_sync(0xffffffffu, p_lo, 2);
            p_hi += __shfl_xor_sync(0xffffffffu, p_hi, 1);
            p_hi += __shfl_xor_sync(0xffffffffu, p_hi, 2);
            if (tg == 0) {
                S.part[r_lo][warp_n] = p_lo;
                S.part[r_hi][warp_n] = p_hi;
            }
        }
    }
    __syncthreads();

    float hv = 0.0f;
    if (t < MS) {
        hv = S.part[t][0] + S.part[t][1];
        hv -= prev[(size_t)b * MS + t] * 100.0f;
    }
    {
        float v = (t < MS) ? hv * hv : 0.0f;
        S.red[t] = v; __syncthreads();
        for (int s = 128; s > 0; s >>= 1) {
            if (t < s) S.red[t] += S.red[t + s];
            __syncthreads();
        }
        float nrm = fmaxf(sqrtf(S.red[0]), 1e-12f);
        __syncthreads();
        if (t < MS) hv /= nrm;
    }
    float z = (t < MS) ? hv + gumbelf(noise_sm[(size_t)b * MS + t]) : -INFINITY;
    float y = 0.0f;
    {
        S.red[t] = z; __syncthreads();
        for (int s = 128; s > 0; s >>= 1) {
            if (t < s) S.red[t] = fmaxf(S.red[t], S.red[t + s]);
            __syncthreads();
        }
        float zmax = S.red[0]; __syncthreads();
        float e = (t < MS) ? expf(z - zmax) : 0.0f;
        S.red[t] = e; __syncthreads();
        for (int s = 128; s > 0; s >>= 1) {
            if (t < s) S.red[t] += S.red[t + s];
            __syncthreads();
        }
        float es = S.red[0]; __syncthreads();
        y = e / es;
        S.red[t] = (t < MS) ? y : 0.0f; __syncthreads();
        for (int s = 128; s > 0; s >>= 1) {
            if (t < s) S.red[t] = fmaxf(S.red[t], S.red[t + s]);
            __syncthreads();
        }
        float ymax = S.red[0]; __syncthreads();
        if (t < MS) {
            float hard = (y == ymax) ? 1.0f : 0.0f;
            float ri = (hard - y) + y;      // exactly 0 off-support
            S.ri[t] = ri;
            g_ri[(size_t)b * MS + t] = ri;
        }
    }
    __syncthreads();

    if (t < RS) {
        float a = 0.0f;
#pragma unroll 8
        for (int m = 0; m < MS; m++) a += S.ri[m] * S.hm[m][t];
        S.rs[t] = a;
        g_r[(size_t)b * RS + t] = a;
        out[(size_t)b * 576 + HS + t] = a;
    }
    __syncthreads();

    {
        float s0 = 0.0f, s1 = 0.0f;
        for (int cI = t; cI < 832; cI += 256) {
            float v;
            if (cI < 256)      v = x[(size_t)b * XS + cI];
            else if (cI < 768) v = h[(size_t)b * HS + (cI - 256)];
            else               v = S.rs[cI - 768];
            s0 += v * W_full1[cI * 2 + 0];
            s1 += v * W_full1[cI * 2 + 1];
        }
        S.red[t] = s0; __syncthreads();
        for (int s = 128; s > 0; s >>= 1) {
            if (t < s) S.red[t] += S.red[t + s];
            __syncthreads();
        }
        float S0 = S.red[0]; __syncthreads();
        S.red[t] = s1; __syncthreads();
        for (int s = 128; s > 0; s >>= 1) {
            if (t < s) S.red[t] += S.red[t + s];
            __syncthreads();
        }
        float S1 = S.red[0];
        if (t == 0)
            g_ab[b * 2 + 0] = sigm((S0 + bias1[0] + gumbelf(noise_sig[b * 2 + 0])) * (10.0f / 3.0f));
        if (t == 1)
            g_ab[b * 2 + 1] = sigm((S1 + bias1[1] + gumbelf(noise_sig[b * 2 + 1])) * (10.0f / 3.0f));
    }
}

// ---------------- small kernels ----------------
__global__ void k_prep(const float* __restrict__ u)
{
    __shared__ float red[128];
    int b = blockIdx.x, t = threadIdx.x;
    float uv = u[b * MS + t];
    red[t] = uv * uv; __syncthreads();
    for (int s = 64; s > 0; s >>= 1) {
        if (t < s) red[t] += red[t + s];
        __syncthreads();
    }
    float denom = fmaxf(sqrtf(red[0]), 1e-12f);
    g_un[b * MS + t] = uv / denom;
}

__global__ void k_kwk(const float* __restrict__ keys, const float* __restrict__ W_fc)
{
    int m = blockIdx.x, t = threadIdx.x;
    float a = 0.0f;
#pragma unroll 8
    for (int r = 0; r < KS; r++)
        a += keys[m * KS + r] * W_fc[(768 + r) * HQ + t];
    g_kWk[m * HQ + t] = a;
}

__global__ void k_epi(const float* __restrict__ c, const float* __restrict__ bias2,
                      float* __restrict__ out)
{
    int b = blockIdx.x, t = threadIdx.x;   // 256 threads
    for (int j = t; j < HS; j += 256) {
        size_t bj = (size_t)b * HS + j;
        float pre = g_G[bj] + bias2[j];
        float nc0 = tanhf(pre);
        float zi = g_Z[(size_t)b * 1536 + j];
        float zf = g_Z[(size_t)b * 1536 + 512 + j];
        float zo = g_Z[(size_t)b * 1536 + 1024 + j];
        float cc = c[bj];
        float ncv = cc * sigm(zf + 1.0f) + sigm(zi) * nc0;
        float nh = tanhf(ncv) * sigm(zo);
        out[(size_t)b * 576 + j] = nh;
        g_nh[bj] = nh;
    }
}

__global__ __launch_bounds__(256) void k_hw(
    const float* __restrict__ x, const float* __restrict__ W_fc1,
    const float* __restrict__ b_fc1)
{
    __shared__ float Ws[64][64];
    __shared__ float Asb[16][68];
    const int b0 = blockIdx.x * 16;
    const int t = threadIdx.x;
    const int n = t & 63, bl = t >> 6;
    float acc[4] = {0.0f, 0.0f, 0.0f, 0.0f};

    for (int k0 = 0; k0 < 768; k0 += 64) {
#pragma unroll
        for (int i = 0; i < 4; i++) {
            int idx = t + i * 256;
            int row = idx >> 4, c4 = (idx & 15) * 4;
            *(float4*)&Ws[row][c4] = *(const float4*)(W_fc1 + (size_t)(k0 + row) * RS + c4);
        }
        {
            int idx = t;
            int row = idx >> 4, c4 = (idx & 15) * 4;
            int gb = b0 + row, gk = k0 + c4;
            float4 v;
            if (gk < 256) v = *(const float4*)(x + (size_t)gb * XS + gk);
            else          v = *(const float4*)(g_nh + (size_t)gb * HS + (gk - 256));
            *(float4*)&Asb[row][c4] = v;
        }
        __syncthreads();
#pragma unroll 16
        for (int kk = 0; kk < 64; kk++) {
            float w = Ws[kk][n];
#pragma unroll
            for (int i = 0; i < 4; i++) acc[i] += Asb[bl * 4 + i][kk] * w;
        }
        __syncthreads();
    }
    float bb = b_fc1[n];
#pragma unroll
    for (int i = 0; i < 4; i++)
        g_hw[(size_t)(b0 + bl * 4 + i) * RS + n] = acc[i] + bb;
}

__global__ void k_hmem_copy(const float* __restrict__ hmem, float* __restrict__ out)
{
    size_t idx = (size_t)blockIdx.x * 256 + threadIdx.x;
    ((float4*)out)[(size_t)(BSZ * 576 / 4) + idx] = ((const float4*)hmem)[idx];
}

__global__ void k_hmem_fix(const float* __restrict__ hmem, float* __restrict__ out)
{
    __shared__ float w[128];
    const int b = blockIdx.x, t = threadIdx.x;
    w[t] = g_ri[(size_t)b * MS + t];
    __syncthreads();
    for (int m = 0; m < MS; m++) {
        float wm = w[m];
        if (wm != 0.0f && t < RS) {
            float hv = hmem[((size_t)b * MS + m) * RS + t];
            float hwv = g_hw[(size_t)b * RS + t];
            out[(size_t)BSZ * 576 + ((size_t)b * MS + m) * RS + t] =
                hwv * wm + hv * (1.0f - wm);
        }
    }
}

// ---------------- launch ----------------
extern "C" void kernel_launch(void* const* d_in, const int* in_sizes, int n_in,
                              void* d_out, int out_size)
{
    const float* x        = (const float*)d_in[0];
    const float* h        = (const float*)d_in[1];
    const float* c        = (const float*)d_in[2];
    const float* hmem     = (const float*)d_in[3];
    const float* u_t      = (const float*)d_in[4];
    const float* prev     = (const float*)d_in[5];
    const float* W_full   = (const float*)d_in[6];
    const float* bias     = (const float*)d_in[7];
    const float* W_full1  = (const float*)d_in[8];
    const float* bias1    = (const float*)d_in[9];
    const float* W_full2  = (const float*)d_in[10];
    const float* bias2    = (const float*)d_in[11];
    const float* keys     = (const float*)d_in[12];
    const float* vec_a    = (const float*)d_in[13];
    const float* W_fc     = (const float*)d_in[14];
    const float* b_fc     = (const float*)d_in[15];
    const float* W_fc1    = (const float*)d_in[16];
    const float* b_fc1    = (const float*)d_in[17];
    const float* noise_sm = (const float*)d_in[18];
    const float* noise_sig= (const float*)d_in[19];
    float* out = (float*)d_out;

    float *p_r, *p_ab, *p_Z, *p_G;
    cudaGetSymbolAddress((void**)&p_r,  g_r);
    cudaGetSymbolAddress((void**)&p_ab, g_ab);
    cudaGetSymbolAddress((void**)&p_Z,  g_Z);
    cudaGetSymbolAddress((void**)&p_G,  g_G);

    const int MMASMEM = 4 * 128 * APAD * 4;   // 73728 B

    static cudaStream_t s2 = nullptr, s3 = nullptr;
    static cudaEvent_t e1 = nullptr, e2 = nullptr, e_wk = nullptr;
    static bool init_done = false;
    if (!init_done) {
        cudaFuncSetAttribute(k_headsel, cudaFuncAttributeMaxDynamicSharedMemorySize,
                             (int)sizeof(HSmem));
        cudaFuncSetAttribute(mma_big, cudaFuncAttributeMaxDynamicSharedMemorySize, MMASMEM);
        cudaStreamCreateWithFlags(&s2, cudaStreamNonBlocking);
        cudaStreamCreateWithFlags(&s3, cudaStreamNonBlocking);
        cudaEventCreateWithFlags(&e1, cudaEventDisableTiming);
        cudaEventCreateWithFlags(&e2, cudaEventDisableTiming);
        cudaEventCreateWithFlags(&e_wk, cudaEventDisableTiming);
        init_done = true;
    }

    // fork
    cudaEventRecord(e1, 0);
    cudaStreamWaitEvent(s2, e1, 0);
    cudaStreamWaitEvent(s3, e1, 0);

    // s2: bulk hmem copy (no deps)
    k_hmem_copy<<<(BSZ * MS * 16) / 256, 256, 0, s2>>>(hmem, out);
    cudaEventRecord(e2, s2);

    // s3: weight-side prep (transW for mma_big; kwk/wmt for headsel)
    k_transW<<<dim3(26, 64), 256, 0, s3>>>(W_full, W_full2);
    k_kwk<<<MS, HQ, 0, s3>>>(keys, W_fc);
    k_wmt<<<MS, KS, 0, s3>>>(W_fc);
    cudaEventRecord(e_wk, s3);

    // main chain
    k_prep<<<BSZ, 128>>>(u_t);
    gemm_base<<<dim3(7, 16), 256>>>(x, c, W_fc);

    cudaStreamWaitEvent(0, e_wk, 0);
    k_headsel<<<BSZ, 256, sizeof(HSmem)>>>(x, h, hmem, prev, noise_sm, noise_sig,
                                           vec_a, b_fc, W_full1, bias1, out);

    mma_big<<<dim3(16, 16), 256, MMASMEM>>>(x, h, p_r, p_ab, bias, p_Z, p_G);

    k_epi<<<BSZ, 256>>>(c, bias2, out);
    k_hw<<<BSZ / 16, 256>>>(x, W_fc1, b_fc1);

    cudaStreamWaitEvent(0, e2, 0);
    k_hmem_fix<<<BSZ, 128>>>(hmem, out);
}